// round 16
// baseline (speedup 1.0000x reference)
#include <cuda_runtime.h>
#include <cuda_fp16.h>
#include <cstdint>

#define D_DIM 1024
#define BROWS_MAX 16384

// ---------------------------------------------------------------------------
// Scratch (device globals — allocation-free).
// ---------------------------------------------------------------------------
__device__ __align__(128) float g_M0f[D_DIM * D_DIM];
__device__ __align__(128) float g_M1f[D_DIM * D_DIM];

__device__ __align__(128) __half g_Uh[D_DIM * D_DIM];
__device__ __align__(128) __half g_Ul[D_DIM * D_DIM];
__device__ __align__(128) __half g_P0h[D_DIM * D_DIM];
__device__ __align__(128) __half g_P0l[D_DIM * D_DIM];
__device__ __align__(128) __half g_P1h[D_DIM * D_DIM];
__device__ __align__(128) __half g_P1l[D_DIM * D_DIM];
__device__ __align__(128) __half g_M0h[D_DIM * D_DIM];
__device__ __align__(128) __half g_M1h[D_DIM * D_DIM];
__device__ __align__(128) __half g_Eh[BROWS_MAX * D_DIM];

// ---------------------------------------------------------------------------
// PTX helpers
// ---------------------------------------------------------------------------
__device__ __forceinline__ uint32_t smem_u32(const void* p) {
    uint32_t a;
    asm("{ .reg .u64 t; cvta.to.shared.u64 t, %1; cvt.u32.u64 %0, t; }"
        : "=r"(a) : "l"(p));
    return a;
}

#define CP_ASYNC16(dst, src) \
    asm volatile("cp.async.cg.shared.global [%0], [%1], 16;" :: "r"(dst), "l"(src))
#define CP_COMMIT() asm volatile("cp.async.commit_group;" ::: "memory")
#define CP_WAIT(n)  asm volatile("cp.async.wait_group %0;" :: "n"(n) : "memory")

#define LDSM_X4(r0, r1, r2, r3, addr) \
    asm volatile("ldmatrix.sync.aligned.m8n8.x4.shared.b16 {%0,%1,%2,%3}, [%4];" \
        : "=r"(r0), "=r"(r1), "=r"(r2), "=r"(r3) : "r"(addr))
#define LDSM_X4T(r0, r1, r2, r3, addr) \
    asm volatile("ldmatrix.sync.aligned.m8n8.x4.trans.shared.b16 {%0,%1,%2,%3}, [%4];" \
        : "=r"(r0), "=r"(r1), "=r"(r2), "=r"(r3) : "r"(addr))
#define MMA16816(acc, a, b) \
    asm volatile("mma.sync.aligned.m16n8k16.row.col.f32.f16.f16.f32 " \
        "{%0,%1,%2,%3}, {%4,%5,%6,%7}, {%8,%9}, {%0,%1,%2,%3};" \
        : "+f"((acc)[0]), "+f"((acc)[1]), "+f"((acc)[2]), "+f"((acc)[3]) \
        : "r"((a)[0]), "r"((a)[1]), "r"((a)[2]), "r"((a)[3]), "r"((b)[0]), "r"((b)[1]))

__device__ __forceinline__ __half2 hsplit2(float x, float y, float2& rem) {
    __half hx = __float2half_rn(x);
    __half hy = __float2half_rn(y);
    rem.x = x - __half2float(hx);
    rem.y = y - __half2float(hy);
    return __halves2half2(hx, hy);
}

__device__ __forceinline__ void hi_store4(float4 x, __half* hi, size_t i) {
    *reinterpret_cast<__half2*>(hi + i) =
        __halves2half2(__float2half_rn(x.x), __float2half_rn(x.y));
    *reinterpret_cast<__half2*>(hi + i + 2) =
        __halves2half2(__float2half_rn(x.z), __float2half_rn(x.w));
}

__device__ __forceinline__ void split_store4(float4 x, __half* hi, __half* lo, size_t i) {
    float2 r0, r1;
    __half2 h0 = hsplit2(x.x, x.y, r0);
    __half2 h1 = hsplit2(x.z, x.w, r1);
    *reinterpret_cast<__half2*>(hi + i)     = h0;
    *reinterpret_cast<__half2*>(hi + i + 2) = h1;
    *reinterpret_cast<__half2*>(lo + i)     =
        __halves2half2(__float2half_rn(r0.x), __float2half_rn(r0.y));
    *reinterpret_cast<__half2*>(lo + i + 2) =
        __halves2half2(__float2half_rn(r1.x), __float2half_rn(r1.y));
}

// ---------------------------------------------------------------------------
// Prep: Uh/Ul = split(A);  M0f = A+I;  M0h = hi(A+I).
// ---------------------------------------------------------------------------
__global__ void prep_kernel(const float* __restrict__ A,
                            __half* __restrict__ Uh, __half* __restrict__ Ul,
                            float* __restrict__ Mf, __half* __restrict__ Mh) {
    int i = (blockIdx.x * blockDim.x + threadIdx.x) * 4;
    int row = i >> 10;
    int colbase = i & (D_DIM - 1);
    float4 x = *reinterpret_cast<const float4*>(A + i);
    split_store4(x, Uh, Ul, i);
    if (row >= colbase && row < colbase + 4) {
        if (row == colbase)          x.x += 1.0f;
        else if (row == colbase + 1) x.y += 1.0f;
        else if (row == colbase + 2) x.z += 1.0f;
        else                         x.w += 1.0f;
    }
    *reinterpret_cast<float4*>(Mf + i) = x;
    hi_store4(x, Mh, i);
}

// ---------------------------------------------------------------------------
// GEMM problem descriptor (per-CTA selected via blockIdx.z: z==0 -> d0, else d1).
// mode 0 = GEMM;  mode 1 = splitter slice (hi-only split of split_src).
// ---------------------------------------------------------------------------
struct Desc {
    const __half* ah;      // A-side hi
    const __half* bh;      // B-side hi
    const __half* bl;      // B-side lo (unused if !TWOB)
    const float* cin;
    float* cf;
    __half* oh;
    __half* ol;
    const float* split_src;
    int split_n;
    int add_c, out_f32, out_split, out_lo, mode;
};

// ---------------------------------------------------------------------------
// fp16 tensor-core GEMM (mma.m16n8k16.f32.f16.f16.f32), fp32 accum:
//   TWOB=true : V = Ah*Bh + Ah*Bl   (chain: B-side split, 2 passes, BKC=32)
//   TWOB=false: V = Ah*Bh           (main: plain fp16, 1 pass, BKC=64)
// A: [M,1024] row-major; smem rows = 2*BKC bytes;
//    swizzle: BKC=32 -> chunk ^= (r>>1)&3 ; BKC=64 -> chunk ^= r&7.
// B: [1024,1024] row-major (ldmatrix.trans; smem swizzle chunk ^= r&7).
// ---------------------------------------------------------------------------
template <int BM, int BN, int WR, int WC, int STAGES, int BKC, bool TWOB>
__global__ __launch_bounds__(256, 2)
void mma_gemm_kernel(Desc d0, Desc d1,
                     const float* __restrict__ wv, const float* __restrict__ bv,
                     int do_epi) {
    constexpr int KDIM = D_DIM;
    constexpr int WM = BM / WR;
    constexpr int WN = BN / WC;
    constexpr int MT = WM / 16;
    constexpr int NT = WN / 8;
    constexpr int ARB = BKC * 2;           // A smem row bytes
    constexpr int ACH = ARB / 16;          // A 16B chunks per row
    constexpr int AONE = BM * ARB;
    constexpr int BROWB = BN * 2;
    constexpr int BONE = BKC * BROWB;
    constexpr int OFF_BH = AONE;
    constexpr int OFF_BL = AONE + BONE;
    constexpr int SBYTES = AONE + (TWOB ? 2 : 1) * BONE;
    constexpr int BCH = BN / 8;
    constexpr int NAI = BM * ACH / 256;
    constexpr int AR_STEP = 256 / ACH;     // A rows per cp iter
    constexpr int NBI = BKC * BCH / 256;
    constexpr int RSTEP = 256 / BCH;
    constexpr int TT = KDIM / BKC;
    constexpr int KBN = BKC / 16;          // kb steps per chunk

    const Desc d = (blockIdx.z == 0) ? d0 : d1;
    const int tid = threadIdx.x;

    if (d.mode == 1) {     // splitter slice: hi-only split of split_src
        const int cta = blockIdx.y * gridDim.x + blockIdx.x;
        const int nct = gridDim.x * gridDim.y;
        for (size_t i = ((size_t)cta * 256 + tid) * 8; i < (size_t)d.split_n;
             i += (size_t)nct * 256 * 8) {
#pragma unroll
            for (int u = 0; u < 2; u++) {
                float4 x = *reinterpret_cast<const float4*>(d.split_src + i + u * 4);
                hi_store4(x, d.oh, i + u * 4);
            }
        }
        return;
    }

    extern __shared__ char smem[];
    const uint32_t s0 = smem_u32(smem);
    const int lane = tid & 31;
    const int wid = tid >> 5;
    const int wm0 = (wid / WC) * WM;
    const int wn0 = (wid % WC) * WN;
    const int m0 = blockIdx.y * BM;
    const int n0 = blockIdx.x * BN;

    // ---- cp.async addressing (affine, hoisted) ----
    const int r0a = tid / ACH, c0a = tid % ACH;
    uint32_t asw;
    if (BKC == 64) asw = (uint32_t)(c0a ^ (r0a & 7));
    else           asw = (uint32_t)(c0a ^ ((r0a >> 1) & 3));
    const uint32_t adst0 = r0a * ARB + (asw << 4);
    const uint32_t abase0 = (uint32_t)(m0 + r0a) * KDIM + c0a * 8;
    const int r0b = tid / BCH, c0b = tid % BCH;
    const uint32_t bdst0 = r0b * BROWB + ((c0b ^ (r0b & 7)) << 4);
    const uint32_t bbase0 = (uint32_t)r0b * KDIM + n0 + c0b * 8;

    auto issue = [&](int t) {
        if (t >= TT) { CP_COMMIT(); return; }
        const int k0 = t * BKC;
        const uint32_t sa = s0 + (t % STAGES) * SBYTES;
        const __half* pah = d.ah + abase0 + k0;
        const __half* pbh = d.bh + bbase0 + ((uint32_t)k0 << 10);
#pragma unroll
        for (int i = 0; i < NAI; i++)
            CP_ASYNC16(sa + adst0 + i * (AR_STEP * ARB), pah + i * (AR_STEP * KDIM));
#pragma unroll
        for (int i = 0; i < NBI; i++)
            CP_ASYNC16(sa + OFF_BH + bdst0 + i * (RSTEP * BROWB), pbh + i * (RSTEP * KDIM));
        if (TWOB) {
            const __half* pbl = d.bl + bbase0 + ((uint32_t)k0 << 10);
#pragma unroll
            for (int i = 0; i < NBI; i++)
                CP_ASYNC16(sa + OFF_BL + bdst0 + i * (RSTEP * BROWB), pbl + i * (RSTEP * KDIM));
        }
        CP_COMMIT();
    };

    // ---- ldmatrix offsets (hoisted) ----
    uint32_t baseA[MT], seA[MT];
    {
        const int c0 = lane >> 4;
#pragma unroll
        for (int i = 0; i < MT; i++) {
            int row = wm0 + i * 16 + (lane & 15);
            if (BKC == 64) {
                int s = row & 7;
                baseA[i] = row * ARB + ((c0 ^ (s & 1)) << 4);
                seA[i] = (s & 6) << 4;
            } else {
                int s = (row >> 1) & 3;
                baseA[i] = row * ARB + ((c0 ^ (s & 1)) << 4);
                seA[i] = (s & 2) << 4;
            }
        }
    }
    uint32_t bbase[NT / 2];
    {
        const int klane = (lane & 7) + (lane & 8);
        const int c0 = lane >> 4;
#pragma unroll
        for (int j = 0; j < NT / 2; j++) {
            int c = ((wn0 + j * 16) >> 3) + c0;
            bbase[j] = klane * BROWB + ((c ^ (klane & 7)) << 4);
        }
    }

    float acc[MT][NT][4];
#pragma unroll
    for (int i = 0; i < MT; i++)
#pragma unroll
        for (int j = 0; j < NT; j++)
#pragma unroll
            for (int q = 0; q < 4; q++) acc[i][j][q] = 0.0f;

    for (int s = 0; s < STAGES - 1; s++) issue(s);

    for (int t = 0; t < TT; t++) {
        CP_WAIT(STAGES - 2);
        __syncthreads();
        issue(t + STAGES - 1);
        const uint32_t sa = s0 + (t % STAGES) * SBYTES;
#pragma unroll
        for (int kb = 0; kb < KBN; kb++) {
            const uint32_t akoff = ((uint32_t)(kb * 32));
            const uint32_t bkoff = kb * 16 * BROWB;
            // Pass 1: Ah * Bh
            uint32_t afh[MT][4], bfh[NT][2];
#pragma unroll
            for (int i = 0; i < MT; i++)
                LDSM_X4(afh[i][0], afh[i][1], afh[i][2], afh[i][3],
                        sa + baseA[i] + (akoff ^ seA[i]));
#pragma unroll
            for (int j = 0; j < NT / 2; j++)
                LDSM_X4T(bfh[2 * j][0], bfh[2 * j][1], bfh[2 * j + 1][0], bfh[2 * j + 1][1],
                         sa + OFF_BH + bkoff + bbase[j]);
#pragma unroll
            for (int i = 0; i < MT; i++)
#pragma unroll
                for (int j = 0; j < NT; j++) MMA16816(acc[i][j], afh[i], bfh[j]);
            // Pass 2: Ah * Bl (chain only; reuse afh)
            if (TWOB) {
                uint32_t bfl[NT][2];
#pragma unroll
                for (int j = 0; j < NT / 2; j++)
                    LDSM_X4T(bfl[2 * j][0], bfl[2 * j][1], bfl[2 * j + 1][0], bfl[2 * j + 1][1],
                             sa + OFF_BL + bkoff + bbase[j]);
#pragma unroll
                for (int i = 0; i < MT; i++)
#pragma unroll
                    for (int j = 0; j < NT; j++) MMA16816(acc[i][j], afh[i], bfl[j]);
            }
        }
    }

    // Epilogue. C frag: c0,c1 -> (row g, cols q*2,q*2+1); c2,c3 -> row g+8.
    const int g = lane >> 2, q = lane & 3;
#pragma unroll
    for (int i = 0; i < MT; i++) {
#pragma unroll
        for (int j = 0; j < NT; j++) {
            int row0 = m0 + wm0 + i * 16 + g;
            int col = n0 + wn0 + j * 8 + q * 2;
            size_t o0 = (size_t)row0 * KDIM + col;
            size_t o1 = o0 + (size_t)8 * KDIM;
            float2 v0 = make_float2(acc[i][j][0], acc[i][j][1]);
            float2 v1 = make_float2(acc[i][j][2], acc[i][j][3]);
            if (d.add_c) {
                float2 c0 = *reinterpret_cast<const float2*>(d.cin + o0);
                float2 c1 = *reinterpret_cast<const float2*>(d.cin + o1);
                v0.x += c0.x; v0.y += c0.y;
                v1.x += c1.x; v1.y += c1.y;
            }
            if (do_epi) {
                float2 w2 = *reinterpret_cast<const float2*>(wv + col);
                float2 b2 = *reinterpret_cast<const float2*>(bv + col);
                v0.x = fmaf(v0.x, w2.x, b2.x); v0.y = fmaf(v0.y, w2.y, b2.y);
                v1.x = fmaf(v1.x, w2.x, b2.x); v1.y = fmaf(v1.y, w2.y, b2.y);
            }
            if (d.out_f32) {
                *reinterpret_cast<float2*>(d.cf + o0) = v0;
                *reinterpret_cast<float2*>(d.cf + o1) = v1;
            }
            if (d.out_split) {
                if (d.out_lo) {
                    float2 r0, r1;
                    __half2 h0 = hsplit2(v0.x, v0.y, r0);
                    __half2 h1 = hsplit2(v1.x, v1.y, r1);
                    *reinterpret_cast<__half2*>(d.oh + o0) = h0;
                    *reinterpret_cast<__half2*>(d.oh + o1) = h1;
                    *reinterpret_cast<__half2*>(d.ol + o0) =
                        __halves2half2(__float2half_rn(r0.x), __float2half_rn(r0.y));
                    *reinterpret_cast<__half2*>(d.ol + o1) =
                        __halves2half2(__float2half_rn(r1.x), __float2half_rn(r1.y));
                } else {
                    *reinterpret_cast<__half2*>(d.oh + o0) =
                        __halves2half2(__float2half_rn(v0.x), __float2half_rn(v0.y));
                    *reinterpret_cast<__half2*>(d.oh + o1) =
                        __halves2half2(__float2half_rn(v1.x), __float2half_rn(v1.y));
                }
            }
        }
    }
}

// ---------------------------------------------------------------------------
// Host side
// ---------------------------------------------------------------------------
extern "C" void kernel_launch(void* const* d_in, const int* in_sizes, int n_in,
                              void* d_out, int out_size) {
    const float* eps  = (const float*)d_in[0];   // [B, D]
    const float* A    = (const float*)d_in[1];   // [D, D]
    const float* w    = (const float*)d_in[2];   // [D]
    const float* bias = (const float*)d_in[3];   // [D]
    float* out = (float*)d_out;

    const int D = D_DIM;
    const int Brows = in_sizes[0] / D;           // 16384
    const int DD = D * D;

    float *M0f, *M1f;
    __half *Uh, *Ul, *P0h, *P0l, *P1h, *P1l, *M0h, *M1h, *Eh;
    cudaGetSymbolAddress((void**)&M0f, g_M0f);
    cudaGetSymbolAddress((void**)&M1f, g_M1f);
    cudaGetSymbolAddress((void**)&Uh, g_Uh);
    cudaGetSymbolAddress((void**)&Ul, g_Ul);
    cudaGetSymbolAddress((void**)&P0h, g_P0h);
    cudaGetSymbolAddress((void**)&P0l, g_P0l);
    cudaGetSymbolAddress((void**)&P1h, g_P1h);
    cudaGetSymbolAddress((void**)&P1l, g_P1l);
    cudaGetSymbolAddress((void**)&M0h, g_M0h);
    cudaGetSymbolAddress((void**)&M1h, g_M1h);
    cudaGetSymbolAddress((void**)&Eh, g_Eh);

    // Chain 64x64 BK32 two-B: 12KB x4 = 48KB (2 CTAs/SM).
    // Main 128x64 BK64 one-B: 24KB x4 = 96KB (2 CTAs/SM), 2048 CTAs
    //   -> wave imbalance 7/6.92 = 1.012 (vs 4/3.46 = 1.156 at 128x128).
    constexpr int CH_SMEM = 4 * (64 * 64 + 2 * 32 * 64 * 2);
    constexpr int MN_SMEM = 4 * (128 * 128 + 64 * 64 * 2);
    cudaFuncSetAttribute(mma_gemm_kernel<64, 64, 2, 4, 4, 32, true>,
                         cudaFuncAttributeMaxDynamicSharedMemorySize, CH_SMEM);
    cudaFuncSetAttribute(mma_gemm_kernel<128, 64, 4, 2, 4, 64, false>,
                         cudaFuncAttributeMaxDynamicSharedMemorySize, MN_SMEM);

    auto mkdesc = [](const __half* ah, const __half* bh, const __half* bl,
                     const float* cin, float* cf, __half* oh, __half* ol,
                     int add_c, int out_f32, int out_split, int out_lo) {
        Desc d;
        d.ah = ah; d.bh = bh; d.bl = bl;
        d.cin = cin; d.cf = cf; d.oh = oh; d.ol = ol;
        d.split_src = nullptr; d.split_n = 0;
        d.add_c = add_c; d.out_f32 = out_f32; d.out_split = out_split;
        d.out_lo = out_lo; d.mode = 0;
        return d;
    };

    // M = (I+A)(I+A^2)(I+A^4) = sum_{k=0}^{7} A^k.
    prep_kernel<<<DD / 1024, 256>>>(A, Uh, Ul, M0f, M0h);

    // G1: P0 = A*A (z=0, 256 CTAs)  ||  eps hi-split (z=1, 256 CTAs)
    {
        Desc d0 = mkdesc(Uh, Uh, Ul, nullptr, nullptr, P0h, P0l, 0, 0, 1, 1);
        Desc d1 = {};
        d1.mode = 1; d1.split_src = eps; d1.split_n = Brows * D; d1.oh = Eh;
        dim3 grid(D / 64, D / 64, 2);
        mma_gemm_kernel<64, 64, 2, 4, 4, 32, true><<<grid, 256, CH_SMEM>>>(
            d0, d1, nullptr, nullptr, 0);
    }
    // G2 || G3: M1 = M0*P0 + M0 (hi split + f32) ; P1 = P0*P0 (hi+lo)
    {
        Desc d0 = mkdesc(M0h, P0h, P0l, M0f, M1f, M1h, nullptr, 1, 1, 1, 0);
        Desc d1 = mkdesc(P0h, P0h, P0l, nullptr, nullptr, P1h, P1l, 0, 0, 1, 1);
        dim3 grid(D / 64, D / 64, 2);
        mma_gemm_kernel<64, 64, 2, 4, 4, 32, true><<<grid, 256, CH_SMEM>>>(
            d0, d1, nullptr, nullptr, 0);
    }
    // G4: Mfinal = M1*P1 + M1  -> hi only into M0h (main is single-pass)
    {
        Desc d = mkdesc(M1h, P1h, P1l, M1f, nullptr, M0h, nullptr, 1, 0, 1, 0);
        dim3 grid(D / 64, D / 64, 1);
        mma_gemm_kernel<64, 64, 2, 4, 4, 32, true><<<grid, 256, CH_SMEM>>>(
            d, d, nullptr, nullptr, 0);
    }

    // Main: out = (eps_h @ M0h) * w + bias  (plain fp16, 128x64, 2048 CTAs)
    {
        Desc d = mkdesc(Eh, M0h, nullptr, nullptr, out, nullptr, nullptr, 0, 1, 0, 0);
        dim3 grid(D / 64, Brows / 128, 1);
        mma_gemm_kernel<128, 64, 4, 2, 4, 64, false><<<grid, 256, MN_SMEM>>>(
            d, d, w, bias, 1);
    }
}

// round 17
// speedup vs baseline: 1.2095x; 1.2095x over previous
#include <cuda_runtime.h>
#include <cuda_fp16.h>
#include <cstdint>

#define D_DIM 1024
#define BROWS_MAX 16384

// ---------------------------------------------------------------------------
// Scratch (device globals — allocation-free).
// ---------------------------------------------------------------------------
__device__ __align__(128) float g_M0f[D_DIM * D_DIM];
__device__ __align__(128) float g_M1f[D_DIM * D_DIM];

__device__ __align__(128) __half g_Uh[D_DIM * D_DIM];
__device__ __align__(128) __half g_P0h[D_DIM * D_DIM];
__device__ __align__(128) __half g_P1h[D_DIM * D_DIM];
__device__ __align__(128) __half g_M0h[D_DIM * D_DIM];
__device__ __align__(128) __half g_M1h[D_DIM * D_DIM];
__device__ __align__(128) __half g_Eh[BROWS_MAX * D_DIM];

// ---------------------------------------------------------------------------
// PTX helpers
// ---------------------------------------------------------------------------
__device__ __forceinline__ uint32_t smem_u32(const void* p) {
    uint32_t a;
    asm("{ .reg .u64 t; cvta.to.shared.u64 t, %1; cvt.u32.u64 %0, t; }"
        : "=r"(a) : "l"(p));
    return a;
}

#define CP_ASYNC16(dst, src) \
    asm volatile("cp.async.cg.shared.global [%0], [%1], 16;" :: "r"(dst), "l"(src))
#define CP_COMMIT() asm volatile("cp.async.commit_group;" ::: "memory")
#define CP_WAIT(n)  asm volatile("cp.async.wait_group %0;" :: "n"(n) : "memory")

#define LDSM_X4(r0, r1, r2, r3, addr) \
    asm volatile("ldmatrix.sync.aligned.m8n8.x4.shared.b16 {%0,%1,%2,%3}, [%4];" \
        : "=r"(r0), "=r"(r1), "=r"(r2), "=r"(r3) : "r"(addr))
#define LDSM_X4T(r0, r1, r2, r3, addr) \
    asm volatile("ldmatrix.sync.aligned.m8n8.x4.trans.shared.b16 {%0,%1,%2,%3}, [%4];" \
        : "=r"(r0), "=r"(r1), "=r"(r2), "=r"(r3) : "r"(addr))
#define MMA16816(acc, a, b) \
    asm volatile("mma.sync.aligned.m16n8k16.row.col.f32.f16.f16.f32 " \
        "{%0,%1,%2,%3}, {%4,%5,%6,%7}, {%8,%9}, {%0,%1,%2,%3};" \
        : "+f"((acc)[0]), "+f"((acc)[1]), "+f"((acc)[2]), "+f"((acc)[3]) \
        : "r"((a)[0]), "r"((a)[1]), "r"((a)[2]), "r"((a)[3]), "r"((b)[0]), "r"((b)[1]))

__device__ __forceinline__ void hi_store4(float4 x, __half* hi, size_t i) {
    *reinterpret_cast<__half2*>(hi + i) =
        __halves2half2(__float2half_rn(x.x), __float2half_rn(x.y));
    *reinterpret_cast<__half2*>(hi + i + 2) =
        __halves2half2(__float2half_rn(x.z), __float2half_rn(x.w));
}

// ---------------------------------------------------------------------------
// Prep: Uh = hi(A);  M0f = A+I;  M0h = hi(A+I).
// ---------------------------------------------------------------------------
__global__ void prep_kernel(const float* __restrict__ A,
                            __half* __restrict__ Uh,
                            float* __restrict__ Mf, __half* __restrict__ Mh) {
    int i = (blockIdx.x * blockDim.x + threadIdx.x) * 4;
    int row = i >> 10;
    int colbase = i & (D_DIM - 1);
    float4 x = *reinterpret_cast<const float4*>(A + i);
    hi_store4(x, Uh, i);
    if (row >= colbase && row < colbase + 4) {
        if (row == colbase)          x.x += 1.0f;
        else if (row == colbase + 1) x.y += 1.0f;
        else if (row == colbase + 2) x.z += 1.0f;
        else                         x.w += 1.0f;
    }
    *reinterpret_cast<float4*>(Mf + i) = x;
    hi_store4(x, Mh, i);
}

// ---------------------------------------------------------------------------
// GEMM problem descriptor (per-CTA selected via blockIdx.z: z==0 -> d0, else d1).
// mode 0 = GEMM;  mode 1 = splitter slice (hi-only conversion of split_src).
// ---------------------------------------------------------------------------
struct Desc {
    const __half* ah;      // A-side hi [M,1024]
    const __half* bh;      // B-side hi [1024,1024]
    const float* cin;      // fp32 accumulate input (optional)
    float* cf;             // fp32 output (optional)
    __half* oh;            // fp16 hi output (optional)
    const float* split_src;
    int split_n;
    int add_c, out_f32, out_hi, mode;
};

// ---------------------------------------------------------------------------
// Plain-fp16 tensor-core GEMM (mma.m16n8k16.f32.f16.f16.f32), fp32 accum:
//   V = Ah*Bh  (+Cin) (*w+b);  outputs fp32 and/or fp16-hi.
// A: [M,1024] row-major; smem rows = 2*BKC bytes;
//    swizzle: BKC=32 -> chunk ^= (r>>1)&3 ; BKC=64 -> chunk ^= r&7.
// B: [1024,1024] row-major (ldmatrix.trans; smem swizzle chunk ^= r&7).
// ---------------------------------------------------------------------------
template <int BM, int BN, int WR, int WC, int STAGES, int BKC>
__global__ __launch_bounds__(256, 2)
void mma_gemm_kernel(Desc d0, Desc d1,
                     const float* __restrict__ wv, const float* __restrict__ bv,
                     int do_epi) {
    constexpr int KDIM = D_DIM;
    constexpr int WM = BM / WR;
    constexpr int WN = BN / WC;
    constexpr int MT = WM / 16;
    constexpr int NT = WN / 8;
    constexpr int ARB = BKC * 2;           // A smem row bytes
    constexpr int ACH = ARB / 16;          // A 16B chunks per row
    constexpr int AONE = BM * ARB;
    constexpr int BROWB = BN * 2;
    constexpr int BONE = BKC * BROWB;
    constexpr int OFF_BH = AONE;
    constexpr int SBYTES = AONE + BONE;
    constexpr int BCH = BN / 8;
    constexpr int NAI = BM * ACH / 256;
    constexpr int AR_STEP = 256 / ACH;     // A rows per cp iter
    constexpr int NBI = BKC * BCH / 256;
    constexpr int RSTEP = 256 / BCH;
    constexpr int TT = KDIM / BKC;
    constexpr int KBN = BKC / 16;          // kb steps per chunk

    const Desc d = (blockIdx.z == 0) ? d0 : d1;
    const int tid = threadIdx.x;

    if (d.mode == 1) {     // splitter slice: hi-only conversion of split_src
        const int cta = blockIdx.y * gridDim.x + blockIdx.x;
        const int nct = gridDim.x * gridDim.y;
        for (size_t i = ((size_t)cta * 256 + tid) * 8; i < (size_t)d.split_n;
             i += (size_t)nct * 256 * 8) {
#pragma unroll
            for (int u = 0; u < 2; u++) {
                float4 x = *reinterpret_cast<const float4*>(d.split_src + i + u * 4);
                hi_store4(x, d.oh, i + u * 4);
            }
        }
        return;
    }

    extern __shared__ char smem[];
    const uint32_t s0 = smem_u32(smem);
    const int lane = tid & 31;
    const int wid = tid >> 5;
    const int wm0 = (wid / WC) * WM;
    const int wn0 = (wid % WC) * WN;
    const int m0 = blockIdx.y * BM;
    const int n0 = blockIdx.x * BN;

    // ---- cp.async addressing (affine, hoisted) ----
    const int r0a = tid / ACH, c0a = tid % ACH;
    uint32_t asw;
    if (BKC == 64) asw = (uint32_t)(c0a ^ (r0a & 7));
    else           asw = (uint32_t)(c0a ^ ((r0a >> 1) & 3));
    const uint32_t adst0 = r0a * ARB + (asw << 4);
    const uint32_t abase0 = (uint32_t)(m0 + r0a) * KDIM + c0a * 8;
    const int r0b = tid / BCH, c0b = tid % BCH;
    const uint32_t bdst0 = r0b * BROWB + ((c0b ^ (r0b & 7)) << 4);
    const uint32_t bbase0 = (uint32_t)r0b * KDIM + n0 + c0b * 8;

    auto issue = [&](int t) {
        if (t >= TT) { CP_COMMIT(); return; }
        const int k0 = t * BKC;
        const uint32_t sa = s0 + (t % STAGES) * SBYTES;
        const __half* pah = d.ah + abase0 + k0;
        const __half* pbh = d.bh + bbase0 + ((uint32_t)k0 << 10);
#pragma unroll
        for (int i = 0; i < NAI; i++)
            CP_ASYNC16(sa + adst0 + i * (AR_STEP * ARB), pah + i * (AR_STEP * KDIM));
#pragma unroll
        for (int i = 0; i < NBI; i++)
            CP_ASYNC16(sa + OFF_BH + bdst0 + i * (RSTEP * BROWB), pbh + i * (RSTEP * KDIM));
        CP_COMMIT();
    };

    // ---- ldmatrix offsets (hoisted) ----
    uint32_t baseA[MT], seA[MT];
    {
        const int c0 = lane >> 4;
#pragma unroll
        for (int i = 0; i < MT; i++) {
            int row = wm0 + i * 16 + (lane & 15);
            if (BKC == 64) {
                int s = row & 7;
                baseA[i] = row * ARB + ((c0 ^ (s & 1)) << 4);
                seA[i] = (s & 6) << 4;
            } else {
                int s = (row >> 1) & 3;
                baseA[i] = row * ARB + ((c0 ^ (s & 1)) << 4);
                seA[i] = (s & 2) << 4;
            }
        }
    }
    uint32_t bbase[NT / 2];
    {
        const int klane = (lane & 7) + (lane & 8);
        const int c0 = lane >> 4;
#pragma unroll
        for (int j = 0; j < NT / 2; j++) {
            int c = ((wn0 + j * 16) >> 3) + c0;
            bbase[j] = klane * BROWB + ((c ^ (klane & 7)) << 4);
        }
    }

    float acc[MT][NT][4];
#pragma unroll
    for (int i = 0; i < MT; i++)
#pragma unroll
        for (int j = 0; j < NT; j++)
#pragma unroll
            for (int q = 0; q < 4; q++) acc[i][j][q] = 0.0f;

    for (int s = 0; s < STAGES - 1; s++) issue(s);

    for (int t = 0; t < TT; t++) {
        CP_WAIT(STAGES - 2);
        __syncthreads();
        issue(t + STAGES - 1);
        const uint32_t sa = s0 + (t % STAGES) * SBYTES;
#pragma unroll
        for (int kb = 0; kb < KBN; kb++) {
            const uint32_t akoff = ((uint32_t)(kb * 32));
            const uint32_t bkoff = kb * 16 * BROWB;
            uint32_t afh[MT][4], bfh[NT][2];
#pragma unroll
            for (int i = 0; i < MT; i++)
                LDSM_X4(afh[i][0], afh[i][1], afh[i][2], afh[i][3],
                        sa + baseA[i] + (akoff ^ seA[i]));
#pragma unroll
            for (int j = 0; j < NT / 2; j++)
                LDSM_X4T(bfh[2 * j][0], bfh[2 * j][1], bfh[2 * j + 1][0], bfh[2 * j + 1][1],
                         sa + OFF_BH + bkoff + bbase[j]);
#pragma unroll
            for (int i = 0; i < MT; i++)
#pragma unroll
                for (int j = 0; j < NT; j++) MMA16816(acc[i][j], afh[i], bfh[j]);
        }
    }

    // Epilogue. C frag: c0,c1 -> (row g, cols q*2,q*2+1); c2,c3 -> row g+8.
    const int g = lane >> 2, q = lane & 3;
#pragma unroll
    for (int i = 0; i < MT; i++) {
#pragma unroll
        for (int j = 0; j < NT; j++) {
            int row0 = m0 + wm0 + i * 16 + g;
            int col = n0 + wn0 + j * 8 + q * 2;
            size_t o0 = (size_t)row0 * KDIM + col;
            size_t o1 = o0 + (size_t)8 * KDIM;
            float2 v0 = make_float2(acc[i][j][0], acc[i][j][1]);
            float2 v1 = make_float2(acc[i][j][2], acc[i][j][3]);
            if (d.add_c) {
                float2 c0 = *reinterpret_cast<const float2*>(d.cin + o0);
                float2 c1 = *reinterpret_cast<const float2*>(d.cin + o1);
                v0.x += c0.x; v0.y += c0.y;
                v1.x += c1.x; v1.y += c1.y;
            }
            if (do_epi) {
                float2 w2 = *reinterpret_cast<const float2*>(wv + col);
                float2 b2 = *reinterpret_cast<const float2*>(bv + col);
                v0.x = fmaf(v0.x, w2.x, b2.x); v0.y = fmaf(v0.y, w2.y, b2.y);
                v1.x = fmaf(v1.x, w2.x, b2.x); v1.y = fmaf(v1.y, w2.y, b2.y);
            }
            if (d.out_f32) {
                *reinterpret_cast<float2*>(d.cf + o0) = v0;
                *reinterpret_cast<float2*>(d.cf + o1) = v1;
            }
            if (d.out_hi) {
                *reinterpret_cast<__half2*>(d.oh + o0) =
                    __halves2half2(__float2half_rn(v0.x), __float2half_rn(v0.y));
                *reinterpret_cast<__half2*>(d.oh + o1) =
                    __halves2half2(__float2half_rn(v1.x), __float2half_rn(v1.y));
            }
        }
    }
}

// ---------------------------------------------------------------------------
// Host side
// ---------------------------------------------------------------------------
extern "C" void kernel_launch(void* const* d_in, const int* in_sizes, int n_in,
                              void* d_out, int out_size) {
    const float* eps  = (const float*)d_in[0];   // [B, D]
    const float* A    = (const float*)d_in[1];   // [D, D]
    const float* w    = (const float*)d_in[2];   // [D]
    const float* bias = (const float*)d_in[3];   // [D]
    float* out = (float*)d_out;

    const int D = D_DIM;
    const int Brows = in_sizes[0] / D;           // 16384
    const int DD = D * D;

    float *M0f, *M1f;
    __half *Uh, *P0h, *P1h, *M0h, *M1h, *Eh;
    cudaGetSymbolAddress((void**)&M0f, g_M0f);
    cudaGetSymbolAddress((void**)&M1f, g_M1f);
    cudaGetSymbolAddress((void**)&Uh, g_Uh);
    cudaGetSymbolAddress((void**)&P0h, g_P0h);
    cudaGetSymbolAddress((void**)&P1h, g_P1h);
    cudaGetSymbolAddress((void**)&M0h, g_M0h);
    cudaGetSymbolAddress((void**)&M1h, g_M1h);
    cudaGetSymbolAddress((void**)&Eh, g_Eh);

    // Chain 64x64 BK32 one-B: stage = 4K + 4K = 8KB, 4 stages = 32KB (2 CTAs/SM).
    // Main 128x128 BK64 one-B: stage = 16K + 16K = 32KB, 3 stages = 96KB (2 CTAs/SM).
    constexpr int CH_SMEM = 4 * (64 * 64 + 32 * 64 * 2);
    constexpr int MN_SMEM = 3 * (128 * 128 + 64 * 128 * 2);
    cudaFuncSetAttribute(mma_gemm_kernel<64, 64, 2, 4, 4, 32>,
                         cudaFuncAttributeMaxDynamicSharedMemorySize, CH_SMEM);
    cudaFuncSetAttribute(mma_gemm_kernel<128, 128, 2, 4, 3, 64>,
                         cudaFuncAttributeMaxDynamicSharedMemorySize, MN_SMEM);

    auto mkdesc = [](const __half* ah, const __half* bh,
                     const float* cin, float* cf, __half* oh,
                     int add_c, int out_f32, int out_hi) {
        Desc d;
        d.ah = ah; d.bh = bh;
        d.cin = cin; d.cf = cf; d.oh = oh;
        d.split_src = nullptr; d.split_n = 0;
        d.add_c = add_c; d.out_f32 = out_f32; d.out_hi = out_hi; d.mode = 0;
        return d;
    };

    // M = (I+A)(I+A^2)(I+A^4) = sum_{k=0}^{7} A^k.
    // All GEMMs plain fp16 (fp32 accum); chain-product errors carry ~10%
    // relative weight in M (||A^2||_F ~ 3.3 vs ||M||_F ~ 32), so the dropped
    // lo-terms add only ~1e-4 on top of the measured 1.75e-4.
    prep_kernel<<<DD / 1024, 256>>>(A, Uh, M0f, M0h);

    // G1: P0 = A*A (z=0, 256 CTAs)  ||  eps hi-convert (z=1, 256 CTAs)
    {
        Desc d0 = mkdesc(Uh, Uh, nullptr, nullptr, P0h, 0, 0, 1);
        Desc d1 = {};
        d1.mode = 1; d1.split_src = eps; d1.split_n = Brows * D; d1.oh = Eh;
        dim3 grid(D / 64, D / 64, 2);
        mma_gemm_kernel<64, 64, 2, 4, 4, 32><<<grid, 256, CH_SMEM>>>(
            d0, d1, nullptr, nullptr, 0);
    }
    // G2 || G3: M1 = M0*P0 + M0 (f32 + hi) ; P1 = P0*P0 (hi)
    {
        Desc d0 = mkdesc(M0h, P0h, M0f, M1f, M1h, 1, 1, 1);
        Desc d1 = mkdesc(P0h, P0h, nullptr, nullptr, P1h, 0, 0, 1);
        dim3 grid(D / 64, D / 64, 2);
        mma_gemm_kernel<64, 64, 2, 4, 4, 32><<<grid, 256, CH_SMEM>>>(
            d0, d1, nullptr, nullptr, 0);
    }
    // G4: Mfinal = M1*P1 + M1  -> hi into M0h
    {
        Desc d = mkdesc(M1h, P1h, M1f, nullptr, M0h, 1, 0, 1);
        dim3 grid(D / 64, D / 64, 1);
        mma_gemm_kernel<64, 64, 2, 4, 4, 32><<<grid, 256, CH_SMEM>>>(
            d, d, nullptr, nullptr, 0);
    }

    // Main: out = (eps_h @ M0h) * w + bias  (128x128, BK64, 1024 CTAs)
    {
        Desc d = mkdesc(Eh, M0h, nullptr, out, nullptr, 0, 1, 0);
        dim3 grid(D / 128, Brows / 128, 1);
        mma_gemm_kernel<128, 128, 2, 4, 3, 64><<<grid, 256, MN_SMEM>>>(
            d, d, w, bias, 1);
    }
}